// round 11
// baseline (speedup 1.0000x reference)
#include <cuda_runtime.h>
#include <cuda_fp16.h>

#define NMAX 50000
#define NG 512

// ---- scratch (static __device__: no allocation allowed) ----
__device__ __align__(16) __half g_xh[NMAX * 64];   // x in half
__device__ __align__(16) __half g_aggh[NMAX * 64]; // neighbor-sum accumulator (half)
__device__ float    g_h[NMAX * 64];       // hidden after Linear1
__device__ float    g_stats[128];         // [0:64) sum, [64:128) sumsq
__device__ float    g_add[NG * 64];       // segment sum pool
__device__ unsigned g_max[NG * 64];       // segment max pool (relu>=0 -> uint order ok)
__device__ int      g_isI32;              // 1 if indices are int32, 0 if int64

// ---- packed f32x2 helpers (bit-identical fp32 math, 2 FMA/instr) ----
__device__ __forceinline__ unsigned long long pack2(float a, float b) {
    unsigned long long r;
    asm("mov.b64 %0, {%1, %2};" : "=l"(r) : "f"(a), "f"(b));
    return r;
}
__device__ __forceinline__ void unpack2(unsigned long long v, float& a, float& b) {
    asm("mov.b64 {%0, %1}, %2;" : "=f"(a), "=f"(b) : "l"(v));
}
#define FMA2(acc, a2, b2) \
    asm("fma.rn.f32x2 %0, %1, %2, %3;" : "=l"(acc) : "l"(a2), "l"(b2), "l"(acc))

// ============================================================
// K0: pack x->half, zero accumulator/stats/pools, probe idx dtype
// ============================================================
__global__ void k_init(const float* __restrict__ x, const int* __restrict__ ei32, int n8) {
    int tid = blockIdx.x * blockDim.x + threadIdx.x;
    if (tid == 0) {
        int nz = 0;
        #pragma unroll 4
        for (int i = 0; i < 256; i++) nz |= ei32[2 * i + 1];
        g_isI32 = (nz != 0) ? 1 : 0;
    }
    if (tid < n8) {
        const float4* xp = (const float4*)(x + (size_t)tid * 8);
        float4 a = xp[0], b = xp[1];
        __half2 h0 = __float22half2_rn(make_float2(a.x, a.y));
        __half2 h1 = __float22half2_rn(make_float2(a.z, a.w));
        __half2 h2 = __float22half2_rn(make_float2(b.x, b.y));
        __half2 h3 = __float22half2_rn(make_float2(b.z, b.w));
        uint4 o;
        o.x = *(unsigned*)&h0; o.y = *(unsigned*)&h1;
        o.z = *(unsigned*)&h2; o.w = *(unsigned*)&h3;
        *(uint4*)(g_xh + (size_t)tid * 8) = o;
        *(uint4*)(g_aggh + (size_t)tid * 8) = make_uint4(0u, 0u, 0u, 0u);
    }
    if (tid < 128) g_stats[tid] = 0.0f;
    if (tid < NG * 64) { g_add[tid] = 0.0f; g_max[tid] = 0u; }
}

// ============================================================
// K1: edge scatter  aggh[dst] += xh[src]
// 4 threads/edge: each owns a 32B-aligned chunk (16 halves) ->
// two adjacent uint4 loads (one L2 sector, zero waste) + two
// v4.f16x2 vector reductions.
// ============================================================
__global__ void k_edges(const void* __restrict__ ei, int n_edges) {
    int tid = blockIdx.x * blockDim.x + threadIdx.x;
    if (tid >= n_edges * 4) return;
    int e = tid >> 2;
    int c = tid & 3;                 // 32B chunk index
    int s, d;
    if (g_isI32) {
        const int* p = (const int*)ei;
        s = p[e]; d = p[n_edges + e];
    } else {
        const long long* p = (const long long*)ei;
        s = (int)p[e]; d = (int)p[n_edges + e];
    }
    const __half* src = g_xh + ((size_t)s << 6) + (c << 4);
    uint4 v0 = *(const uint4*)(src);
    uint4 v1 = *(const uint4*)(src + 8);
    __half* o = g_aggh + ((size_t)d << 6) + (c << 4);
    asm volatile("red.global.add.noftz.v4.f16x2 [%0], {%1, %2, %3, %4};"
                 :: "l"(o), "r"(v0.x), "r"(v0.y), "r"(v0.z), "r"(v0.w)
                 : "memory");
    asm volatile("red.global.add.noftz.v4.f16x2 [%0], {%1, %2, %3, %4};"
                 :: "l"(o + 8), "r"(v1.x), "r"(v1.y), "r"(v1.z), "r"(v1.w)
                 : "memory");
}

// ---- GEMM inner loop: 4 rows x 4 cols / thread, scalar A reads ----
#define GEMM_CORE(sA, sW, acc01, acc23, rbase, c0)                           \
    _Pragma("unroll 8")                                                      \
    for (int k = 0; k < 64; k++) {                                           \
        ulonglong2 w2 = *(const ulonglong2*)&sW[k * 64 + c0];                \
        _Pragma("unroll")                                                    \
        for (int i = 0; i < 4; i++) {                                        \
            float a = sA[(rbase + i) * 68 + k];                              \
            unsigned long long aa = pack2(a, a);                             \
            FMA2(acc01[i], aa, w2.x);                                        \
            FMA2(acc23[i], aa, w2.y);                                        \
        }                                                                    \
    }

// ============================================================
// K2: h = (x + aggh) @ W1 + b1, accumulate BN sum/sumsq
// ============================================================
__global__ __launch_bounds__(256) void k_gemm1(const float* __restrict__ x,
                                               const float* __restrict__ W1,
                                               const float* __restrict__ b1, int n_nodes) {
    __shared__ float sW[64 * 64];
    __shared__ float sA[64 * 68];
    __shared__ float sSum[64], sSq[64];
    int tid = threadIdx.x;
    int row0 = blockIdx.x * 64;

    for (int i = tid; i < 1024; i += 256) ((float4*)sW)[i] = ((const float4*)W1)[i];
    if (tid < 64) { sSum[tid] = 0.0f; sSq[tid] = 0.0f; }
    for (int i = tid; i < 1024; i += 256) {
        int r = i >> 4, c4 = i & 15, gr = row0 + r;
        float4 v = make_float4(0.f, 0.f, 0.f, 0.f);
        if (gr < n_nodes) {
            v = *(const float4*)(x + (size_t)gr * 64 + c4 * 4);
            uint2 hh = *(const uint2*)(g_aggh + (size_t)gr * 64 + c4 * 4);
            float2 f0 = __half22float2(*(__half2*)&hh.x);
            float2 f1 = __half22float2(*(__half2*)&hh.y);
            v.x += f0.x; v.y += f0.y; v.z += f1.x; v.w += f1.y;
        }
        *(float4*)&sA[r * 68 + c4 * 4] = v;
    }
    __syncthreads();

    int rg = tid >> 4;
    int c0 = (tid & 15) * 4;
    int rbase = rg * 4;
    float4 bb = *(const float4*)(b1 + c0);
    unsigned long long acc01[4], acc23[4];
    #pragma unroll
    for (int i = 0; i < 4; i++) { acc01[i] = pack2(bb.x, bb.y); acc23[i] = pack2(bb.z, bb.w); }

    GEMM_CORE(sA, sW, acc01, acc23, rbase, c0)

    float cs[4] = {0, 0, 0, 0}, cq[4] = {0, 0, 0, 0};
    #pragma unroll
    for (int i = 0; i < 4; i++) {
        int gr = row0 + rbase + i;
        if (gr < n_nodes) {
            float a0, a1, a2, a3;
            unpack2(acc01[i], a0, a1);
            unpack2(acc23[i], a2, a3);
            *(float4*)(g_h + (size_t)gr * 64 + c0) = make_float4(a0, a1, a2, a3);
            cs[0] += a0; cs[1] += a1; cs[2] += a2; cs[3] += a3;
            cq[0] += a0 * a0; cq[1] += a1 * a1; cq[2] += a2 * a2; cq[3] += a3 * a3;
        }
    }
    #pragma unroll
    for (int j = 0; j < 4; j++) {
        atomicAdd(&sSum[c0 + j], cs[j]);
        atomicAdd(&sSq[c0 + j], cq[j]);
    }
    __syncthreads();
    if (tid < 64) {
        atomicAdd(&g_stats[tid], sSum[tid]);
        atomicAdd(&g_stats[64 + tid], sSq[tid]);
    }
}

// ============================================================
// K4: h2 = relu(relu(bn(h)) @ W2 + b2); pooled into g_add/g_max
// ============================================================
__device__ __forceinline__ void pool_flush(int b, int c0, const float s[4], const float m[4]) {
    float* pa = g_add + (size_t)b * 64 + c0;
    asm volatile("red.global.add.v4.f32 [%0], {%1, %2, %3, %4};"
                 :: "l"(pa), "f"(s[0]), "f"(s[1]), "f"(s[2]), "f"(s[3])
                 : "memory");
    unsigned* pm = g_max + (size_t)b * 64 + c0;
    atomicMax(pm + 0, __float_as_uint(m[0]));
    atomicMax(pm + 1, __float_as_uint(m[1]));
    atomicMax(pm + 2, __float_as_uint(m[2]));
    atomicMax(pm + 3, __float_as_uint(m[3]));
}

__global__ __launch_bounds__(256) void k_gemm2(const float* __restrict__ W2,
                                               const float* __restrict__ b2,
                                               const float* __restrict__ gamma,
                                               const float* __restrict__ beta,
                                               const void* __restrict__ batch,
                                               int n_nodes, float inv_n) {
    __shared__ float sW[64 * 64];
    __shared__ float sA[64 * 68];
    __shared__ float sScale[64], sShift[64];
    int tid = threadIdx.x;
    int row0 = blockIdx.x * 64;

    for (int i = tid; i < 1024; i += 256) ((float4*)sW)[i] = ((const float4*)W2)[i];
    if (tid < 64) {
        float mean = g_stats[tid] * inv_n;
        float var  = g_stats[64 + tid] * inv_n - mean * mean;
        float a = gamma[tid] * rsqrtf(var + 1e-5f);
        sScale[tid] = a;
        sShift[tid] = beta[tid] - mean * a;
    }
    __syncthreads();
    for (int i = tid; i < 1024; i += 256) {
        int r = i >> 4, c4 = i & 15, gr = row0 + r, k0 = c4 * 4;
        float4 v = make_float4(0.f, 0.f, 0.f, 0.f);
        if (gr < n_nodes) {
            v = *(const float4*)(g_h + (size_t)gr * 64 + k0);
            v.x = fmaxf(v.x * sScale[k0 + 0] + sShift[k0 + 0], 0.f);
            v.y = fmaxf(v.y * sScale[k0 + 1] + sShift[k0 + 1], 0.f);
            v.z = fmaxf(v.z * sScale[k0 + 2] + sShift[k0 + 2], 0.f);
            v.w = fmaxf(v.w * sScale[k0 + 3] + sShift[k0 + 3], 0.f);
        }
        *(float4*)&sA[r * 68 + k0] = v;
    }
    __syncthreads();

    int rg = tid >> 4;
    int c0 = (tid & 15) * 4;
    int rbase = rg * 4;
    float4 bb = *(const float4*)(b2 + c0);
    unsigned long long acc01[4], acc23[4];
    #pragma unroll
    for (int i = 0; i < 4; i++) { acc01[i] = pack2(bb.x, bb.y); acc23[i] = pack2(bb.z, bb.w); }

    GEMM_CORE(sA, sW, acc01, acc23, rbase, c0)

    // fused pooling: merge consecutive rows of the same graph (batch is sorted)
    const int* b32 = (const int*)batch;
    const long long* b64 = (const long long*)batch;
    int isI32 = g_isI32;
    int prevb = -1;
    float s[4] = {0, 0, 0, 0}, m[4] = {0, 0, 0, 0};
    #pragma unroll
    for (int i = 0; i < 4; i++) {
        int gr = row0 + rbase + i;
        if (gr >= n_nodes) break;
        int b = isI32 ? b32[gr] : (int)b64[gr];
        float v[4];
        float a0, a1, a2, a3;
        unpack2(acc01[i], a0, a1);
        unpack2(acc23[i], a2, a3);
        v[0] = fmaxf(a0, 0.f); v[1] = fmaxf(a1, 0.f);
        v[2] = fmaxf(a2, 0.f); v[3] = fmaxf(a3, 0.f);
        if (b != prevb) {
            if (prevb >= 0) pool_flush(prevb, c0, s, m);
            prevb = b;
            #pragma unroll
            for (int j = 0; j < 4; j++) { s[j] = v[j]; m[j] = v[j]; }
        } else {
            #pragma unroll
            for (int j = 0; j < 4; j++) { s[j] += v[j]; m[j] = fmaxf(m[j], v[j]); }
        }
    }
    if (prevb >= 0) pool_flush(prevb, c0, s, m);
}

// ============================================================
// K5: head MLP, 4 graphs per block
// ============================================================
__global__ __launch_bounds__(128) void k_final(const float* __restrict__ Wl1,
                                               const float* __restrict__ bl1,
                                               const float* __restrict__ Wl2,
                                               const float* __restrict__ bl2,
                                               float* __restrict__ out, int out_size) {
    int g0 = blockIdx.x * 4;
    int j = threadIdx.x;
    __shared__ float sg[4][128];
    __shared__ float red[4][128];
    #pragma unroll
    for (int q = 0; q < 4; q++) {
        int g = g0 + q;
        sg[q][j] = (j < 64) ? g_add[g * 64 + j]
                            : __uint_as_float(g_max[g * 64 + (j - 64)]);
    }
    __syncthreads();
    float bj = bl1[j];
    float t[4] = {bj, bj, bj, bj};
    #pragma unroll 4
    for (int k = 0; k < 128; k++) {
        float w = Wl1[k * 128 + j];
        #pragma unroll
        for (int q = 0; q < 4; q++) t[q] += sg[q][k] * w;
    }
    float w2 = Wl2[j];
    #pragma unroll
    for (int q = 0; q < 4; q++) red[q][j] = fmaxf(t[q], 0.f) * w2;
    __syncthreads();
    for (int sft = 64; sft > 0; sft >>= 1) {
        if (j < sft) {
            #pragma unroll
            for (int q = 0; q < 4; q++) red[q][j] += red[q][j + sft];
        }
        __syncthreads();
    }
    if (j < 4) {
        float logit = red[j][0] + bl2[0];
        int g = g0 + j;
        out[g] = 1.0f / (1.0f + expf(-logit));
        if (out_size >= 2 * NG) out[NG + g] = logit;
    }
}

// ============================================================
extern "C" void kernel_launch(void* const* d_in, const int* in_sizes, int n_in,
                              void* d_out, int out_size) {
    const float* x     = (const float*)d_in[0];
    const void*  ei    = d_in[1];
    const void*  batch = d_in[2];
    const float* W1    = (const float*)d_in[3];
    const float* b1    = (const float*)d_in[4];
    const float* gamma = (const float*)d_in[5];
    const float* beta  = (const float*)d_in[6];
    const float* W2    = (const float*)d_in[7];
    const float* b2    = (const float*)d_in[8];
    const float* Wl1   = (const float*)d_in[9];
    const float* bl1   = (const float*)d_in[10];
    const float* Wl2   = (const float*)d_in[11];
    const float* bl2   = (const float*)d_in[12];
    float* out = (float*)d_out;

    int n_nodes = in_sizes[0] / 64;
    if (n_nodes > NMAX) n_nodes = NMAX;
    int n_edges = in_sizes[1] / 2;

    int n8 = n_nodes * 8;
    int initN = (n8 > NG * 64) ? n8 : NG * 64;
    k_init<<<(initN + 255) / 256, 256>>>(x, (const int*)ei, n8);

    long long etot = (long long)n_edges * 4;
    k_edges<<<(int)((etot + 255) / 256), 256>>>(ei, n_edges);

    int nb = (n_nodes + 63) / 64;
    k_gemm1<<<nb, 256>>>(x, W1, b1, n_nodes);
    k_gemm2<<<nb, 256>>>(W2, b2, gamma, beta, batch, n_nodes, 1.0f / (float)n_nodes);
    k_final<<<NG / 4, 128>>>(Wl1, bl1, Wl2, bl2, out, out_size);
}

// round 12
// speedup vs baseline: 1.1248x; 1.1248x over previous
#include <cuda_runtime.h>
#include <cuda_fp16.h>

#define NMAX 50000
#define NG 512

// ---- scratch (static __device__: no allocation allowed) ----
__device__ __align__(16) __half g_xh[NMAX * 64];   // x in half
__device__ __align__(16) __half g_aggh[NMAX * 64]; // neighbor-sum accumulator (half)
__device__ float    g_h[NMAX * 64];       // hidden after Linear1
__device__ float    g_stats[128];         // [0:64) sum, [64:128) sumsq
__device__ float    g_add[NG * 64];       // segment sum pool
__device__ unsigned g_max[NG * 64];       // segment max pool (relu>=0 -> uint order ok)
__device__ int      g_isI32;              // 1 if indices are int32, 0 if int64

// ---- packed f32x2 helpers (bit-identical fp32 math, 2 FMA/instr) ----
__device__ __forceinline__ unsigned long long pack2(float a, float b) {
    unsigned long long r;
    asm("mov.b64 %0, {%1, %2};" : "=l"(r) : "f"(a), "f"(b));
    return r;
}
__device__ __forceinline__ void unpack2(unsigned long long v, float& a, float& b) {
    asm("mov.b64 {%0, %1}, %2;" : "=f"(a), "=f"(b) : "l"(v));
}
#define FMA2(acc, a2, b2) \
    asm("fma.rn.f32x2 %0, %1, %2, %3;" : "=l"(acc) : "l"(a2), "l"(b2), "l"(acc))

// ============================================================
// K0: pack x->half, zero accumulator/stats/pools, probe idx dtype
// ============================================================
__global__ void k_init(const float* __restrict__ x, const int* __restrict__ ei32, int n8) {
    int tid = blockIdx.x * blockDim.x + threadIdx.x;
    if (tid == 0) {
        int nz = 0;
        #pragma unroll 4
        for (int i = 0; i < 256; i++) nz |= ei32[2 * i + 1];
        g_isI32 = (nz != 0) ? 1 : 0;
    }
    if (tid < n8) {
        const float4* xp = (const float4*)(x + (size_t)tid * 8);
        float4 a = xp[0], b = xp[1];
        __half2 h0 = __float22half2_rn(make_float2(a.x, a.y));
        __half2 h1 = __float22half2_rn(make_float2(a.z, a.w));
        __half2 h2 = __float22half2_rn(make_float2(b.x, b.y));
        __half2 h3 = __float22half2_rn(make_float2(b.z, b.w));
        uint4 o;
        o.x = *(unsigned*)&h0; o.y = *(unsigned*)&h1;
        o.z = *(unsigned*)&h2; o.w = *(unsigned*)&h3;
        *(uint4*)(g_xh + (size_t)tid * 8) = o;
        *(uint4*)(g_aggh + (size_t)tid * 8) = make_uint4(0u, 0u, 0u, 0u);
    }
    if (tid < 128) g_stats[tid] = 0.0f;
    if (tid < NG * 64) { g_add[tid] = 0.0f; g_max[tid] = 0u; }
}

// ============================================================
// K1: edge scatter  aggh[dst] += xh[src]
// 8 threads/edge: one 16B gather + one v4.f16x2 vector reduction
// (8 consecutive threads cover the full 128B row: fully coalesced)
// ============================================================
__global__ void k_edges(const void* __restrict__ ei, int n_edges) {
    int tid = blockIdx.x * blockDim.x + threadIdx.x;
    if (tid >= n_edges * 8) return;
    int e = tid >> 3;
    int c = tid & 7;
    int s, d;
    if (g_isI32) {
        const int* p = (const int*)ei;
        s = p[e]; d = p[n_edges + e];
    } else {
        const long long* p = (const long long*)ei;
        s = (int)p[e]; d = (int)p[n_edges + e];
    }
    uint4 v = *(const uint4*)(g_xh + ((size_t)s << 6) + (c << 3));
    __half* o = g_aggh + ((size_t)d << 6) + (c << 3);
    asm volatile("red.global.add.noftz.v4.f16x2 [%0], {%1, %2, %3, %4};"
                 :: "l"(o), "r"(v.x), "r"(v.y), "r"(v.z), "r"(v.w)
                 : "memory");
}

// ---- GEMM inner loop: 4 rows x 4 cols / thread, scalar A reads ----
#define GEMM_CORE(sA, sW, acc01, acc23, rbase, c0)                           \
    _Pragma("unroll 8")                                                      \
    for (int k = 0; k < 64; k++) {                                           \
        ulonglong2 w2 = *(const ulonglong2*)&sW[k * 64 + c0];                \
        _Pragma("unroll")                                                    \
        for (int i = 0; i < 4; i++) {                                        \
            float a = sA[(rbase + i) * 68 + k];                              \
            unsigned long long aa = pack2(a, a);                             \
            FMA2(acc01[i], aa, w2.x);                                        \
            FMA2(acc23[i], aa, w2.y);                                        \
        }                                                                    \
    }

// ============================================================
// K2: h = (x + aggh) @ W1 + b1, accumulate BN sum/sumsq
// forced 6 CTAs/SM (reg cap 42) to lift residency 32 -> 48 warps
// ============================================================
__global__ __launch_bounds__(256, 6) void k_gemm1(const float* __restrict__ x,
                                                  const float* __restrict__ W1,
                                                  const float* __restrict__ b1, int n_nodes) {
    __shared__ float sW[64 * 64];
    __shared__ float sA[64 * 68];
    __shared__ float sSum[64], sSq[64];
    int tid = threadIdx.x;
    int row0 = blockIdx.x * 64;

    for (int i = tid; i < 1024; i += 256) ((float4*)sW)[i] = ((const float4*)W1)[i];
    if (tid < 64) { sSum[tid] = 0.0f; sSq[tid] = 0.0f; }
    for (int i = tid; i < 1024; i += 256) {
        int r = i >> 4, c4 = i & 15, gr = row0 + r;
        float4 v = make_float4(0.f, 0.f, 0.f, 0.f);
        if (gr < n_nodes) {
            v = *(const float4*)(x + (size_t)gr * 64 + c4 * 4);
            uint2 hh = *(const uint2*)(g_aggh + (size_t)gr * 64 + c4 * 4);
            float2 f0 = __half22float2(*(__half2*)&hh.x);
            float2 f1 = __half22float2(*(__half2*)&hh.y);
            v.x += f0.x; v.y += f0.y; v.z += f1.x; v.w += f1.y;
        }
        *(float4*)&sA[r * 68 + c4 * 4] = v;
    }
    __syncthreads();

    int rg = tid >> 4;
    int c0 = (tid & 15) * 4;
    int rbase = rg * 4;
    float4 bb = *(const float4*)(b1 + c0);
    unsigned long long acc01[4], acc23[4];
    #pragma unroll
    for (int i = 0; i < 4; i++) { acc01[i] = pack2(bb.x, bb.y); acc23[i] = pack2(bb.z, bb.w); }

    GEMM_CORE(sA, sW, acc01, acc23, rbase, c0)

    float cs[4] = {0, 0, 0, 0}, cq[4] = {0, 0, 0, 0};
    #pragma unroll
    for (int i = 0; i < 4; i++) {
        int gr = row0 + rbase + i;
        if (gr < n_nodes) {
            float a0, a1, a2, a3;
            unpack2(acc01[i], a0, a1);
            unpack2(acc23[i], a2, a3);
            *(float4*)(g_h + (size_t)gr * 64 + c0) = make_float4(a0, a1, a2, a3);
            cs[0] += a0; cs[1] += a1; cs[2] += a2; cs[3] += a3;
            cq[0] += a0 * a0; cq[1] += a1 * a1; cq[2] += a2 * a2; cq[3] += a3 * a3;
        }
    }
    #pragma unroll
    for (int j = 0; j < 4; j++) {
        atomicAdd(&sSum[c0 + j], cs[j]);
        atomicAdd(&sSq[c0 + j], cq[j]);
    }
    __syncthreads();
    if (tid < 64) {
        atomicAdd(&g_stats[tid], sSum[tid]);
        atomicAdd(&g_stats[64 + tid], sSq[tid]);
    }
}

// ============================================================
// K4: h2 = relu(relu(bn(h)) @ W2 + b2); pooled into g_add/g_max
// ============================================================
__device__ __forceinline__ void pool_flush(int b, int c0, const float s[4], const float m[4]) {
    float* pa = g_add + (size_t)b * 64 + c0;
    asm volatile("red.global.add.v4.f32 [%0], {%1, %2, %3, %4};"
                 :: "l"(pa), "f"(s[0]), "f"(s[1]), "f"(s[2]), "f"(s[3])
                 : "memory");
    unsigned* pm = g_max + (size_t)b * 64 + c0;
    atomicMax(pm + 0, __float_as_uint(m[0]));
    atomicMax(pm + 1, __float_as_uint(m[1]));
    atomicMax(pm + 2, __float_as_uint(m[2]));
    atomicMax(pm + 3, __float_as_uint(m[3]));
}

__global__ __launch_bounds__(256, 6) void k_gemm2(const float* __restrict__ W2,
                                                  const float* __restrict__ b2,
                                                  const float* __restrict__ gamma,
                                                  const float* __restrict__ beta,
                                                  const void* __restrict__ batch,
                                                  int n_nodes, float inv_n) {
    __shared__ float sW[64 * 64];
    __shared__ float sA[64 * 68];
    __shared__ float sScale[64], sShift[64];
    int tid = threadIdx.x;
    int row0 = blockIdx.x * 64;

    for (int i = tid; i < 1024; i += 256) ((float4*)sW)[i] = ((const float4*)W2)[i];
    if (tid < 64) {
        float mean = g_stats[tid] * inv_n;
        float var  = g_stats[64 + tid] * inv_n - mean * mean;
        float a = gamma[tid] * rsqrtf(var + 1e-5f);
        sScale[tid] = a;
        sShift[tid] = beta[tid] - mean * a;
    }
    __syncthreads();
    for (int i = tid; i < 1024; i += 256) {
        int r = i >> 4, c4 = i & 15, gr = row0 + r, k0 = c4 * 4;
        float4 v = make_float4(0.f, 0.f, 0.f, 0.f);
        if (gr < n_nodes) {
            v = *(const float4*)(g_h + (size_t)gr * 64 + k0);
            v.x = fmaxf(v.x * sScale[k0 + 0] + sShift[k0 + 0], 0.f);
            v.y = fmaxf(v.y * sScale[k0 + 1] + sShift[k0 + 1], 0.f);
            v.z = fmaxf(v.z * sScale[k0 + 2] + sShift[k0 + 2], 0.f);
            v.w = fmaxf(v.w * sScale[k0 + 3] + sShift[k0 + 3], 0.f);
        }
        *(float4*)&sA[r * 68 + k0] = v;
    }
    __syncthreads();

    int rg = tid >> 4;
    int c0 = (tid & 15) * 4;
    int rbase = rg * 4;
    float4 bb = *(const float4*)(b2 + c0);
    unsigned long long acc01[4], acc23[4];
    #pragma unroll
    for (int i = 0; i < 4; i++) { acc01[i] = pack2(bb.x, bb.y); acc23[i] = pack2(bb.z, bb.w); }

    GEMM_CORE(sA, sW, acc01, acc23, rbase, c0)

    // fused pooling: merge consecutive rows of the same graph (batch is sorted)
    const int* b32 = (const int*)batch;
    const long long* b64 = (const long long*)batch;
    int isI32 = g_isI32;
    int prevb = -1;
    float s[4] = {0, 0, 0, 0}, m[4] = {0, 0, 0, 0};
    #pragma unroll
    for (int i = 0; i < 4; i++) {
        int gr = row0 + rbase + i;
        if (gr >= n_nodes) break;
        int b = isI32 ? b32[gr] : (int)b64[gr];
        float v[4];
        float a0, a1, a2, a3;
        unpack2(acc01[i], a0, a1);
        unpack2(acc23[i], a2, a3);
        v[0] = fmaxf(a0, 0.f); v[1] = fmaxf(a1, 0.f);
        v[2] = fmaxf(a2, 0.f); v[3] = fmaxf(a3, 0.f);
        if (b != prevb) {
            if (prevb >= 0) pool_flush(prevb, c0, s, m);
            prevb = b;
            #pragma unroll
            for (int j = 0; j < 4; j++) { s[j] = v[j]; m[j] = v[j]; }
        } else {
            #pragma unroll
            for (int j = 0; j < 4; j++) { s[j] += v[j]; m[j] = fmaxf(m[j], v[j]); }
        }
    }
    if (prevb >= 0) pool_flush(prevb, c0, s, m);
}

// ============================================================
// K5: head MLP, 4 graphs per block
// ============================================================
__global__ __launch_bounds__(128) void k_final(const float* __restrict__ Wl1,
                                               const float* __restrict__ bl1,
                                               const float* __restrict__ Wl2,
                                               const float* __restrict__ bl2,
                                               float* __restrict__ out, int out_size) {
    int g0 = blockIdx.x * 4;
    int j = threadIdx.x;
    __shared__ float sg[4][128];
    __shared__ float red[4][128];
    #pragma unroll
    for (int q = 0; q < 4; q++) {
        int g = g0 + q;
        sg[q][j] = (j < 64) ? g_add[g * 64 + j]
                            : __uint_as_float(g_max[g * 64 + (j - 64)]);
    }
    __syncthreads();
    float bj = bl1[j];
    float t[4] = {bj, bj, bj, bj};
    #pragma unroll 4
    for (int k = 0; k < 128; k++) {
        float w = Wl1[k * 128 + j];
        #pragma unroll
        for (int q = 0; q < 4; q++) t[q] += sg[q][k] * w;
    }
    float w2 = Wl2[j];
    #pragma unroll
    for (int q = 0; q < 4; q++) red[q][j] = fmaxf(t[q], 0.f) * w2;
    __syncthreads();
    for (int sft = 64; sft > 0; sft >>= 1) {
        if (j < sft) {
            #pragma unroll
            for (int q = 0; q < 4; q++) red[q][j] += red[q][j + sft];
        }
        __syncthreads();
    }
    if (j < 4) {
        float logit = red[j][0] + bl2[0];
        int g = g0 + j;
        out[g] = 1.0f / (1.0f + expf(-logit));
        if (out_size >= 2 * NG) out[NG + g] = logit;
    }
}

// ============================================================
extern "C" void kernel_launch(void* const* d_in, const int* in_sizes, int n_in,
                              void* d_out, int out_size) {
    const float* x     = (const float*)d_in[0];
    const void*  ei    = d_in[1];
    const void*  batch = d_in[2];
    const float* W1    = (const float*)d_in[3];
    const float* b1    = (const float*)d_in[4];
    const float* gamma = (const float*)d_in[5];
    const float* beta  = (const float*)d_in[6];
    const float* W2    = (const float*)d_in[7];
    const float* b2    = (const float*)d_in[8];
    const float* Wl1   = (const float*)d_in[9];
    const float* bl1   = (const float*)d_in[10];
    const float* Wl2   = (const float*)d_in[11];
    const float* bl2   = (const float*)d_in[12];
    float* out = (float*)d_out;

    int n_nodes = in_sizes[0] / 64;
    if (n_nodes > NMAX) n_nodes = NMAX;
    int n_edges = in_sizes[1] / 2;

    int n8 = n_nodes * 8;
    int initN = (n8 > NG * 64) ? n8 : NG * 64;
    k_init<<<(initN + 255) / 256, 256>>>(x, (const int*)ei, n8);

    long long etot = (long long)n_edges * 8;
    k_edges<<<(int)((etot + 255) / 256), 256>>>(ei, n_edges);

    int nb = (n_nodes + 63) / 64;
    k_gemm1<<<nb, 256>>>(x, W1, b1, n_nodes);
    k_gemm2<<<nb, 256>>>(W2, b2, gamma, beta, batch, n_nodes, 1.0f / (float)n_nodes);
    k_final<<<NG / 4, 128>>>(Wl1, bl1, Wl2, bl2, out, out_size);
}